// round 10
// baseline (speedup 1.0000x reference)
#include <cuda_runtime.h>
#include <cuda_bf16.h>
#include <stdint.h>
#include <math.h>

#define Hh 160
#define Ww 160
#define Bb 4
#define Cc 64
#define Oo 64
#define NOC 192            // 64 folded pm + 128 qn rows
#define KTOT 576           // k = c*9 + kk (natural order)
#define NTH 256
#define TP 32
#define NCHUNK 36          // K chunks of 16

// window geometry: rows [h-9, h+10] (20), cols [w0i-9, w0i+41] (51), stride 52
#define WROWS 20
#define WCOLS 51
#define WSTR 52
#define WBYTES (WROWS * WSTR * 4)          // 4160

// A (pixel) buffer: 32 rows, [hi 576 bf16][lo 576 bf16][pad] stride 2352B
#define A_STRIDE 2352
#define OFF_A 0
#define A_BYTES (32 * A_STRIDE)            // 75264
// per-warp B rings: 8 warps x 2 bufs x (24 rows x 80B) = 30720
#define OFF_B A_BYTES
#define B_ROWB 80
#define B_BUFW (24 * B_ROWB)               // 1920 per warp per buf
#define SMEM_BYTES (OFF_B + 8 * 2 * B_BUFW)   // 105984

// scratch aliases inside B region (dead before first weight cp.async)
#define OFF_GEO  OFF_B                     // 8 planes x 288 x 4B = 9216
#define OFF_SOFF (OFF_B + 9216)            // 2 x 288 x 4B = 2304
#define OFF_SX   (OFF_B + 11520)           // 64 x 32 x 4B = 8192 (dead after A1)
#define OFF_WIN  (OFF_B + 11520)           // 2 window bufs: 8320B (alias s_x)

__device__ __align__(16) __nv_bfloat16 g_Whi[NOC * KTOT];
__device__ __align__(16) __nv_bfloat16 g_Wlo[NOC * KTOT];

// ---------------------------------------------------------------------------
__device__ __forceinline__ uint32_t smem_u32(const void* p) {
    uint32_t a;
    asm("{ .reg .u64 t; cvta.to.shared.u64 t, %1; cvt.u32.u64 %0, t; }"
        : "=r"(a) : "l"(p));
    return a;
}
__device__ __forceinline__ void ldsm4(uint32_t* r, uint32_t a) {
    asm volatile("ldmatrix.sync.aligned.m8n8.x4.shared.b16 {%0,%1,%2,%3}, [%4];"
        : "=r"(r[0]), "=r"(r[1]), "=r"(r[2]), "=r"(r[3]) : "r"(a));
}
__device__ __forceinline__ void ldsm2(uint32_t* r, uint32_t a) {
    asm volatile("ldmatrix.sync.aligned.m8n8.x2.shared.b16 {%0,%1}, [%2];"
        : "=r"(r[0]), "=r"(r[1]) : "r"(a));
}
__device__ __forceinline__ void mma16816(float* d, const uint32_t* a,
                                         const uint32_t* b) {
    asm volatile("mma.sync.aligned.m16n8k16.row.col.f32.bf16.bf16.f32 "
        "{%0,%1,%2,%3}, {%4,%5,%6,%7}, {%8,%9}, {%0,%1,%2,%3};"
        : "+f"(d[0]), "+f"(d[1]), "+f"(d[2]), "+f"(d[3])
        : "r"(a[0]), "r"(a[1]), "r"(a[2]), "r"(a[3]), "r"(b[0]), "r"(b[1]));
}
#define CP_ASYNC16(dst, src) \
    asm volatile("cp.async.cg.shared.global [%0], [%1], 16;" \
                 :: "r"(dst), "l"(src) : "memory")
#define CP_ASYNC4(dst, src) \
    asm volatile("cp.async.ca.shared.global [%0], [%1], 4;" \
                 :: "r"(dst), "l"(src) : "memory")
#define CP_COMMIT() asm volatile("cp.async.commit_group;" ::: "memory")
#define CP_WAIT1()  asm volatile("cp.async.wait_group 1;" ::: "memory")
#define CP_WAIT0()  asm volatile("cp.async.wait_group 0;" ::: "memory")

// ---------------------------------------------------------------------------
// prep: fold + bf16-split weights, layout [n][k] row-major, k natural
// ---------------------------------------------------------------------------
__global__ void prep_kernel(const float* __restrict__ w_m,
                            const float* __restrict__ w_n) {
    int idx = blockIdx.x * blockDim.x + threadIdx.x;
    if (idx >= NOC * KTOT) return;
    int n = idx / KTOT;
    int k = idx - n * KTOT;
    float v;
    if (n < 64) v = w_m[n * KTOT + k] + w_m[(n + 64) * KTOT + k];
    else        v = w_n[(n - 64) * KTOT + k];
    __nv_bfloat16 h = __float2bfloat16(v);
    g_Whi[idx] = h;
    g_Wlo[idx] = __float2bfloat16(v - __bfloat162float(h));
}

// ---------------------------------------------------------------------------
// fused kernel: one CTA = 32 px (one h row, 32 w) x 192 output rows
// ---------------------------------------------------------------------------
__global__ void __launch_bounds__(NTH, 2)
pala_mma_kernel(const float* __restrict__ x,
                const float* __restrict__ off_w,
                const float* __restrict__ off_b,
                const float* __restrict__ w0v,
                float* __restrict__ out) {
    extern __shared__ char sm[];
    const uint32_t sb = smem_u32(sm);
    const int tid = threadIdx.x, wid = tid >> 5, lane = tid & 31;
    const int w0i = blockIdx.x * TP;
    const int h = blockIdx.y;
    const int b = blockIdx.z;
    const float* xb = x + (size_t)b * (Cc * Hh * Ww);

    // --- Phase A0: stage x column tile [64c][32px] ---
    float* s_x = (float*)(sm + OFF_SX);
    for (int i = tid; i < Cc * TP; i += NTH) {
        int c = i >> 5, p = i & 31;
        s_x[i] = xb[(c * Hh + h) * Ww + w0i + p];
    }
    __syncthreads();

    // --- Phase A1: offset 1x1 conv + clip + tanh soft limit ---
    float* s_off = (float*)(sm + OFF_SOFF);      // [2][9][32]
    for (int i = tid; i < 18 * TP; i += NTH) {
        int o = i >> 5, p = i & 31;
        float acc = off_b[o];
        const float* wr = off_w + o * Cc;
        #pragma unroll 8
        for (int c = 0; c < Cc; c++) acc += wr[c] * s_x[c * TP + p];
        float lo, hi;
        if ((o & 1) == 0) { lo = -(float)h; hi = (float)(Hh - h); }
        else              { int gx = w0i + p; lo = -(float)gx; hi = (float)(Ww - gx); }
        float v = fminf(fmaxf(acc, lo), hi);
        if (fabsf(v) >= 8.0f) v = 8.0f * tanhf(v * 0.125f);
        s_off[(o & 1) * 288 + (o >> 1) * TP + p] = v;
    }
    __syncthreads();

    // --- Phase A2: bilinear geometry, WINDOW-relative indices + weights ---
    // window origin: (h-9, w0i-9); valid corners always land inside it.
    int*   gI = (int*)(sm + OFF_GEO);
    float* gF = (float*)(sm + OFF_GEO);
    for (int i = tid; i < 288; i += NTH) {
        int kk = i >> 5, p = i & 31;
        float oy = s_off[i];
        float ox = s_off[288 + i];
        float py = (float)(h - 1 + kk / 3) + oy;
        float px = (float)(w0i + p - 1 + kk % 3) + ox;
        float y0f = floorf(py), x0f = floorf(px);
        float wy = py - y0f, wx = px - x0f;
        int y0 = (int)y0f, x0 = (int)x0f;
        int y1 = y0 + 1, x1 = x0 + 1;
        float vy0 = (y0 >= 0 && y0 < Hh) ? 1.f : 0.f;
        float vy1 = (y1 >= 0 && y1 < Hh) ? 1.f : 0.f;
        float vx0 = (x0 >= 0 && x0 < Ww) ? 1.f : 0.f;
        float vx1 = (x1 >= 0 && x1 < Ww) ? 1.f : 0.f;
        int wy0 = min(max(y0 - (h - 9), 0), WROWS - 1);
        int wy1 = min(max(y1 - (h - 9), 0), WROWS - 1);
        int wx0 = min(max(x0 - (w0i - 9), 0), WCOLS - 1);
        int wx1 = min(max(x1 - (w0i - 9), 0), WCOLS - 1);
        gI[0 * 288 + i] = wy0 * WSTR + wx0;
        gI[1 * 288 + i] = wy0 * WSTR + wx1;
        gI[2 * 288 + i] = wy1 * WSTR + wx0;
        gI[3 * 288 + i] = wy1 * WSTR + wx1;
        gF[4 * 288 + i] = (1.f - wy) * (1.f - wx) * vy0 * vx0;
        gF[5 * 288 + i] = (1.f - wy) * wx         * vy0 * vx1;
        gF[6 * 288 + i] = wy * (1.f - wx)         * vy1 * vx0;
        gF[7 * 288 + i] = wy * wx                 * vy1 * vx1;
    }
    __syncthreads();   // s_x dead; window bufs may now alias it

    // --- Phase B: windowed sampling, per-channel, cp.async double-buffered ---
    // window load for channel c into buf (edge-clamped -> always finite)
    #define WIN_LOAD(c, buf) do { \
        const float* xc_ = xb + (c) * (Hh * Ww); \
        uint32_t wdst_ = sb + OFF_WIN + (uint32_t)(buf) * WBYTES; \
        _Pragma("unroll") \
        for (int u = 0; u < 4; u++) { \
            int i_ = tid + u * NTH; \
            if (i_ < WROWS * WCOLS) { \
                int wr_ = i_ / WCOLS, wc_ = i_ - wr_ * WCOLS; \
                int gy_ = min(max(h - 9 + wr_, 0), Hh - 1); \
                int gx_ = min(max(w0i - 9 + wc_, 0), Ww - 1); \
                CP_ASYNC4(wdst_ + (uint32_t)(wr_ * WSTR + wc_) * 4, \
                          xc_ + gy_ * Ww + gx_); \
            } \
        } \
        CP_COMMIT(); \
    } while (0)

    WIN_LOAD(0, 0);
    for (int c = 0; c < Cc; c++) {
        if (c + 1 < Cc) { WIN_LOAD(c + 1, (c + 1) & 1); CP_WAIT1(); }
        else            { CP_WAIT0(); }
        __syncthreads();    // window c visible to all threads
        const float* wb = (const float*)(sm + OFF_WIN + (uint32_t)(c & 1) * WBYTES);
        #pragma unroll
        for (int u = 0; u < 2; u++) {
            int i = tid + u * NTH;
            if (i < 288) {
                int kk = i >> 5, p = i & 31;
                float v = gF[4 * 288 + i] * wb[gI[i]]
                        + gF[5 * 288 + i] * wb[gI[288 + i]]
                        + gF[6 * 288 + i] * wb[gI[2 * 288 + i]]
                        + gF[7 * 288 + i] * wb[gI[3 * 288 + i]];
                __nv_bfloat16 hbf = __float2bfloat16(v);
                __nv_bfloat16 lbf = __float2bfloat16(v - __bfloat162float(hbf));
                char* row = sm + OFF_A + p * A_STRIDE;
                int t = c * 9 + kk;
                *(__nv_bfloat16*)(row + 2 * t) = hbf;
                *(__nv_bfloat16*)(row + 1152 + 2 * t) = lbf;
            }
        }
        __syncthreads();    // sampling(c) done before buf[(c)&1]... wait:
                            // next iter issues WIN_LOAD(c+2) into buf[c&1];
                            // this barrier orders those writes after our reads.
    }
    // A complete; geo/window scratch (B region) now dead (barrier above).

    // --- Phase C: warp-independent MMA GEMM, KC=16, per-warp cp.async ring ---
    const int n0 = wid * 24;
    const int grp = lane >> 3;
    const int aRow = (grp & 1) * 8 + (lane & 7);
    const int aK8 = (grp >> 1) * 8;
    const int b4off = ((grp >> 1) * 8 + (lane & 7)) * B_ROWB + (grp & 1) * 16;
    const int l16 = lane & 15;
    const int b2off = (16 + (l16 & 7)) * B_ROWB + (l16 >> 3) * 16;
    const uint32_t warpB = sb + OFF_B + (uint32_t)wid * (2 * B_BUFW);

    #define CP_CHUNK(ck, buf) do { \
        _Pragma("unroll") \
        for (int u = 0; u < 3; u++) { \
            int i = lane + 32 * u; \
            int nl = i >> 2, q = i & 3, half = q >> 1, qq = q & 1; \
            const __nv_bfloat16* src = (half ? g_Wlo : g_Whi) \
                + (n0 + nl) * KTOT + (ck) * 16 + qq * 8; \
            uint32_t dst = warpB + (buf) * B_BUFW + nl * B_ROWB \
                         + half * 32 + qq * 16; \
            CP_ASYNC16(dst, src); \
        } \
        CP_COMMIT(); \
    } while (0)

    float acc[2][3][4];
    #pragma unroll
    for (int mt = 0; mt < 2; mt++)
        #pragma unroll
        for (int j = 0; j < 3; j++)
            #pragma unroll
            for (int q = 0; q < 4; q++) acc[mt][j][q] = 0.f;

    CP_CHUNK(0, 0);
    CP_CHUNK(1, 1);

    for (int ck = 0; ck < NCHUNK; ck++) {
        if (ck == NCHUNK - 1) { CP_WAIT0(); } else { CP_WAIT1(); }
        __syncwarp();
        const uint32_t bufB = warpB + (uint32_t)(ck & 1) * B_BUFW;
        const int k0 = ck * 16;

        uint32_t af[2][2][4];
        #pragma unroll
        for (int mt = 0; mt < 2; mt++) {
            uint32_t base = sb + OFF_A + (uint32_t)((mt * 16 + aRow) * A_STRIDE);
            ldsm4(af[mt][0], base + 2 * (k0 + aK8));          // hi
            ldsm4(af[mt][1], base + 1152 + 2 * (k0 + aK8));   // lo
        }
        uint32_t b01[2][4], b2[2][2];
        #pragma unroll
        for (int hl = 0; hl < 2; hl++) {
            ldsm4(b01[hl], bufB + b4off + hl * 32);
            ldsm2(b2[hl],  bufB + b2off + hl * 32);
        }
        #pragma unroll
        for (int mt = 0; mt < 2; mt++) {
            #pragma unroll
            for (int j = 0; j < 3; j++) {
                const uint32_t* bh = (j < 2) ? &b01[0][j * 2] : b2[0];
                const uint32_t* bl = (j < 2) ? &b01[1][j * 2] : b2[1];
                mma16816(acc[mt][j], af[mt][0], bh);   // hi*hi
                mma16816(acc[mt][j], af[mt][1], bh);   // lo*hi
                mma16816(acc[mt][j], af[mt][0], bl);   // hi*lo
            }
        }
        if (ck < NCHUNK - 2) CP_CHUNK(ck + 2, ck & 1);
    }
    __syncthreads();   // all warps done with B region before res staging

    // --- stage accumulators to smem res[n][m], stride 33 floats ---
    float* res = (float*)(sm + OFF_B);
    {
        const int g = lane >> 2, tig = lane & 3;
        #pragma unroll
        for (int mt = 0; mt < 2; mt++) {
            #pragma unroll
            for (int j = 0; j < 3; j++) {
                int nb = n0 + j * 8 + tig * 2;
                int mb = mt * 16 + g;
                res[nb * 33 + mb]           = acc[mt][j][0];
                res[(nb + 1) * 33 + mb]     = acc[mt][j][1];
                res[nb * 33 + mb + 8]       = acc[mt][j][2];
                res[(nb + 1) * 33 + mb + 8] = acc[mt][j][3];
            }
        }
    }
    __syncthreads();

    // --- epilogue: (pm + w0) / (1 + |qa| + |qb|) ---
    for (int i = tid; i < Oo * TP; i += NTH) {
        int c = i >> 5, p = i & 31;
        float pm = res[c * 33 + p] + __ldg(w0v + c);
        float den = 1.0f + fabsf(res[(64 + c) * 33 + p])
                         + fabsf(res[(128 + c) * 33 + p]);
        out[(((size_t)b * Oo + c) * Hh + h) * Ww + w0i + p] = pm / den;
    }
    #undef CP_CHUNK
    #undef WIN_LOAD
}

// ---------------------------------------------------------------------------
extern "C" void kernel_launch(void* const* d_in, const int* in_sizes, int n_in,
                              void* d_out, int out_size) {
    (void)in_sizes; (void)n_in; (void)out_size;
    const float* x     = (const float*)d_in[0];
    const float* off_w = (const float*)d_in[1];
    const float* off_b = (const float*)d_in[2];
    const float* w_m   = (const float*)d_in[3];
    const float* w_n   = (const float*)d_in[4];
    const float* w0    = (const float*)d_in[5];
    float* out = (float*)d_out;

    prep_kernel<<<(NOC * KTOT + 255) / 256, 256>>>(w_m, w_n);

    cudaFuncSetAttribute(pala_mma_kernel,
                         cudaFuncAttributeMaxDynamicSharedMemorySize, SMEM_BYTES);
    dim3 grid(Ww / TP, Hh, Bb);
    pala_mma_kernel<<<grid, NTH, SMEM_BYTES>>>(x, off_w, off_b, w0, out);
}

// round 13
// speedup vs baseline: 1.3681x; 1.3681x over previous
#include <cuda_runtime.h>
#include <cuda_bf16.h>
#include <stdint.h>
#include <math.h>

#define Hh 160
#define Ww 160
#define Bb 4
#define Cc 64
#define Oo 64
#define NOC 192            // 64 folded pm + 128 qn rows
#define KTOT 576           // k = c*9 + kk (natural order)
#define NTH 256
#define TP 32
#define NCHUNK 36          // K chunks of 16

// A tile: k-major, 576 rows x [hi 32 bf16 | lo 32 bf16 | pad16] stride 144B
#define A_KSTR 144
#define OFF_A 0
#define A_BYTES (KTOT * A_KSTR)            // 82944
// per-warp B rings: 8 warps x 2 bufs x (24 rows x 80B) = 30720
#define OFF_B A_BYTES
#define B_ROWB 80
#define B_BUFW (24 * B_ROWB)               // 1920 per warp per buf
#define SMEM_BYTES (OFF_B + 8 * 2 * B_BUFW)   // 113664

// scratch aliases inside B region
#define OFF_GEO  OFF_B                     // 8 planes x 288 x 4B = 9216 (lives all of phase B)
#define OFF_WIN  (OFF_B + 9216)            // 2 bufs x 2ch x 4480B = 17920 (loads start after A2)
#define OFF_SOFF (OFF_B + 9216)            // 2304 (dead after A2; overlaps windows safely)
#define OFF_SX   (OFF_B + 11520)           // 8192 (dead after A1)

// window: rows h-9..h+10 (20), cols w0i-12..w0i+43 (56 floats, 16B-aligned)
#define WROWS 20
#define WCOLS 56
#define WCH_BYTES (WROWS * WCOLS * 4)      // 4480

__device__ __align__(16) __nv_bfloat16 g_Whi[NOC * KTOT];
__device__ __align__(16) __nv_bfloat16 g_Wlo[NOC * KTOT];

// ---------------------------------------------------------------------------
__device__ __forceinline__ uint32_t smem_u32(const void* p) {
    uint32_t a;
    asm("{ .reg .u64 t; cvta.to.shared.u64 t, %1; cvt.u32.u64 %0, t; }"
        : "=r"(a) : "l"(p));
    return a;
}
__device__ __forceinline__ void ldsm4(uint32_t* r, uint32_t a) {
    asm volatile("ldmatrix.sync.aligned.m8n8.x4.shared.b16 {%0,%1,%2,%3}, [%4];"
        : "=r"(r[0]), "=r"(r[1]), "=r"(r[2]), "=r"(r[3]) : "r"(a));
}
__device__ __forceinline__ void ldsm4t(uint32_t* r, uint32_t a) {
    asm volatile("ldmatrix.sync.aligned.m8n8.x4.trans.shared.b16 {%0,%1,%2,%3}, [%4];"
        : "=r"(r[0]), "=r"(r[1]), "=r"(r[2]), "=r"(r[3]) : "r"(a));
}
__device__ __forceinline__ void ldsm2(uint32_t* r, uint32_t a) {
    asm volatile("ldmatrix.sync.aligned.m8n8.x2.shared.b16 {%0,%1}, [%2];"
        : "=r"(r[0]), "=r"(r[1]) : "r"(a));
}
__device__ __forceinline__ void mma16816(float* d, const uint32_t* a,
                                         const uint32_t* b) {
    asm volatile("mma.sync.aligned.m16n8k16.row.col.f32.bf16.bf16.f32 "
        "{%0,%1,%2,%3}, {%4,%5,%6,%7}, {%8,%9}, {%0,%1,%2,%3};"
        : "+f"(d[0]), "+f"(d[1]), "+f"(d[2]), "+f"(d[3])
        : "r"(a[0]), "r"(a[1]), "r"(a[2]), "r"(a[3]), "r"(b[0]), "r"(b[1]));
}
#define CP_ASYNC16(dst, src) \
    asm volatile("cp.async.cg.shared.global [%0], [%1], 16;" \
                 :: "r"(dst), "l"(src) : "memory")
#define CP_COMMIT() asm volatile("cp.async.commit_group;" ::: "memory")
#define CP_WAIT1()  asm volatile("cp.async.wait_group 1;" ::: "memory")
#define CP_WAIT0()  asm volatile("cp.async.wait_group 0;" ::: "memory")

// ---------------------------------------------------------------------------
// prep: fold + bf16-split weights, layout [n][k] row-major, k natural
// ---------------------------------------------------------------------------
__global__ void prep_kernel(const float* __restrict__ w_m,
                            const float* __restrict__ w_n) {
    int idx = blockIdx.x * blockDim.x + threadIdx.x;
    if (idx >= NOC * KTOT) return;
    int n = idx / KTOT;
    int k = idx - n * KTOT;
    float v;
    if (n < 64) v = w_m[n * KTOT + k] + w_m[(n + 64) * KTOT + k];
    else        v = w_n[(n - 64) * KTOT + k];
    __nv_bfloat16 h = __float2bfloat16(v);
    g_Whi[idx] = h;
    g_Wlo[idx] = __float2bfloat16(v - __bfloat162float(h));
}

// ---------------------------------------------------------------------------
// fused kernel: one CTA = 32 px (one h row, 32 w) x 192 output rows
// ---------------------------------------------------------------------------
__global__ void __launch_bounds__(NTH, 2)
pala_mma_kernel(const float* __restrict__ x,
                const float* __restrict__ off_w,
                const float* __restrict__ off_b,
                const float* __restrict__ w0v,
                float* __restrict__ out) {
    extern __shared__ char sm[];
    const uint32_t sb = smem_u32(sm);
    const int tid = threadIdx.x, wid = tid >> 5, lane = tid & 31;
    const int w0i = blockIdx.x * TP;
    const int h = blockIdx.y;
    const int b = blockIdx.z;
    const float* xb = x + (size_t)b * (Cc * Hh * Ww);

    // --- Phase A0: stage x column tile [64c][32px] ---
    float* s_x = (float*)(sm + OFF_SX);
    for (int i = tid; i < Cc * TP; i += NTH) {
        int c = i >> 5, p = i & 31;
        s_x[i] = xb[(c * Hh + h) * Ww + w0i + p];
    }
    __syncthreads();

    // --- Phase A1: offset 1x1 conv + clip + tanh soft limit ---
    float* s_off = (float*)(sm + OFF_SOFF);      // [2][9][32]
    for (int i = tid; i < 18 * TP; i += NTH) {
        int o = i >> 5, p = i & 31;
        float acc = off_b[o];
        const float* wr = off_w + o * Cc;
        #pragma unroll 8
        for (int c = 0; c < Cc; c++) acc += wr[c] * s_x[c * TP + p];
        float lo, hi;
        if ((o & 1) == 0) { lo = -(float)h; hi = (float)(Hh - h); }
        else              { int gx = w0i + p; lo = -(float)gx; hi = (float)(Ww - gx); }
        float v = fminf(fmaxf(acc, lo), hi);
        if (fabsf(v) >= 8.0f) v = 8.0f * tanhf(v * 0.125f);
        s_off[(o & 1) * 288 + (o >> 1) * TP + p] = v;
    }
    __syncthreads();

    // --- Phase A2: bilinear geometry, WINDOW-relative indices + weights ---
    // window origin: (h-9, w0i-12), 20 rows x 56 cols
    int*   gI = (int*)(sm + OFF_GEO);
    float* gF = (float*)(sm + OFF_GEO);
    for (int i = tid; i < 288; i += NTH) {
        int kk = i >> 5, p = i & 31;
        float oy = s_off[i];
        float ox = s_off[288 + i];
        float py = (float)(h - 1 + kk / 3) + oy;
        float px = (float)(w0i + p - 1 + kk % 3) + ox;
        float y0f = floorf(py), x0f = floorf(px);
        float wy = py - y0f, wx = px - x0f;
        int y0 = (int)y0f, x0 = (int)x0f;
        int y1 = y0 + 1, x1 = x0 + 1;
        float vy0 = (y0 >= 0 && y0 < Hh) ? 1.f : 0.f;
        float vy1 = (y1 >= 0 && y1 < Hh) ? 1.f : 0.f;
        float vx0 = (x0 >= 0 && x0 < Ww) ? 1.f : 0.f;
        float vx1 = (x1 >= 0 && x1 < Ww) ? 1.f : 0.f;
        int wy0 = min(max(y0 - (h - 9), 0), WROWS - 1);
        int wy1 = min(max(y1 - (h - 9), 0), WROWS - 1);
        int wx0 = min(max(x0 - (w0i - 12), 0), WCOLS - 1);
        int wx1 = min(max(x1 - (w0i - 12), 0), WCOLS - 1);
        gI[0 * 288 + i] = wy0 * WCOLS + wx0;
        gI[1 * 288 + i] = wy0 * WCOLS + wx1;
        gI[2 * 288 + i] = wy1 * WCOLS + wx0;
        gI[3 * 288 + i] = wy1 * WCOLS + wx1;
        gF[4 * 288 + i] = (1.f - wy) * (1.f - wx) * vy0 * vx0;
        gF[5 * 288 + i] = (1.f - wy) * wx         * vy0 * vx1;
        gF[6 * 288 + i] = wy * (1.f - wx)         * vy1 * vx0;
        gF[7 * 288 + i] = wy * wx                 * vy1 * vx1;
    }
    __syncthreads();   // s_off/s_x dead; window bufs may now use their space

    // --- per-warp geometry cache: warp w owns k-rows {w, w+8, w+16(<18)} ---
    // row r (0..17): channel-parity u = r>=9, kk = r - 9u
    int nR = (wid < 2) ? 3 : 2;
    int kks[3], us[3];
    int gi0[3], gi1[3], gi2[3], gi3[3];
    float gf0[3], gf1[3], gf2[3], gf3[3];
    #pragma unroll
    for (int j = 0; j < 3; j++) {
        if (j < nR) {
            int r = wid + 8 * j;
            int u = (r >= 9) ? 1 : 0;
            int kk = r - 9 * u;
            kks[j] = kk; us[j] = u;
            int i = kk * TP + lane;
            gi0[j] = gI[i];            gi1[j] = gI[288 + i];
            gi2[j] = gI[2 * 288 + i];  gi3[j] = gI[3 * 288 + i];
            gf0[j] = gF[4 * 288 + i];  gf1[j] = gF[5 * 288 + i];
            gf2[j] = gF[6 * 288 + i];  gf3[j] = gF[7 * 288 + i];
        }
    }

    // --- Phase B: windowed sampling, 2-channel groups, double-buffered ---
    // 16B-aligned cp.async; OOB blocks redirected in-image (read only at wgt 0)
    #define WIN_LOAD2(g) do { \
        uint32_t wdst_ = sb + OFF_WIN + (uint32_t)((g) & 1) * (2 * WCH_BYTES); \
        for (int j_ = tid; j_ < 560; j_ += NTH) { \
            int u_ = j_ / 280, rem_ = j_ - u_ * 280; \
            int wr_ = rem_ / 14, c4_ = rem_ - wr_ * 14; \
            int gy_ = min(max(h - 9 + wr_, 0), Hh - 1); \
            int gx_ = min(max(w0i - 12 + c4_ * 4, 0), Ww - 4); \
            CP_ASYNC16(wdst_ + (uint32_t)(u_ * WCH_BYTES) \
                             + (uint32_t)(wr_ * WCOLS + c4_ * 4) * 4, \
                       xb + (2 * (g) + u_) * (Hh * Ww) + gy_ * Ww + gx_); \
        } \
        CP_COMMIT(); \
    } while (0)

    WIN_LOAD2(0);
    WIN_LOAD2(1);
    for (int g = 0; g < 32; g++) {
        if (g == 31) { CP_WAIT0(); } else { CP_WAIT1(); }
        __syncthreads();                 // window g visible to all warps
        const float* wbase = (const float*)(sm + OFF_WIN
                                            + (uint32_t)(g & 1) * (2 * WCH_BYTES));
        #pragma unroll
        for (int j = 0; j < 3; j++) {
            if (j < nR) {
                const float* wb = wbase + us[j] * (WROWS * WCOLS);
                float v = gf0[j] * wb[gi0[j]] + gf1[j] * wb[gi1[j]]
                        + gf2[j] * wb[gi2[j]] + gf3[j] * wb[gi3[j]];
                __nv_bfloat16 hbf = __float2bfloat16(v);
                __nv_bfloat16 lbf = __float2bfloat16(v - __bfloat162float(hbf));
                int t = (2 * g + us[j]) * 9 + kks[j];
                char* rowp = sm + OFF_A + t * A_KSTR;
                *(__nv_bfloat16*)(rowp + 2 * lane) = hbf;       // coalesced
                *(__nv_bfloat16*)(rowp + 64 + 2 * lane) = lbf;  // coalesced
            }
        }
        __syncthreads();                 // reads done before buf reuse
        if (g < 30) WIN_LOAD2(g + 2);
    }
    // A complete (final barrier above); geo/window scratch now dead

    // --- Phase C: warp-independent MMA GEMM, KC=16, per-warp cp.async ring ---
    const int n0 = wid * 24;
    const int grp = lane >> 3;
    // A (k-major) trans-ldmatrix lane address base:
    //   k-row offset = (grp>>1)*8 + (lane&7); m-byte = mt*32 + (grp&1)*16
    const uint32_t aBase = sb + OFF_A
        + (uint32_t)(((lane >> 4) * 8 + (lane & 7)) * A_KSTR)
        + (uint32_t)(((lane >> 3) & 1) * 16);
    const int b4off = ((grp >> 1) * 8 + (lane & 7)) * B_ROWB + (grp & 1) * 16;
    const int l16 = lane & 15;
    const int b2off = (16 + (l16 & 7)) * B_ROWB + (l16 >> 3) * 16;
    const uint32_t warpB = sb + OFF_B + (uint32_t)wid * (2 * B_BUFW);

    #define CP_CHUNK(ck, buf) do { \
        _Pragma("unroll") \
        for (int u = 0; u < 3; u++) { \
            int i = lane + 32 * u; \
            int nl = i >> 2, q = i & 3, half = q >> 1, qq = q & 1; \
            const __nv_bfloat16* src = (half ? g_Wlo : g_Whi) \
                + (n0 + nl) * KTOT + (ck) * 16 + qq * 8; \
            uint32_t dst = warpB + (buf) * B_BUFW + nl * B_ROWB \
                         + half * 32 + qq * 16; \
            CP_ASYNC16(dst, src); \
        } \
        CP_COMMIT(); \
    } while (0)

    float acc[2][3][4];
    #pragma unroll
    for (int mt = 0; mt < 2; mt++)
        #pragma unroll
        for (int j = 0; j < 3; j++)
            #pragma unroll
            for (int q = 0; q < 4; q++) acc[mt][j][q] = 0.f;

    CP_CHUNK(0, 0);
    CP_CHUNK(1, 1);

    for (int ck = 0; ck < NCHUNK; ck++) {
        if (ck == NCHUNK - 1) { CP_WAIT0(); } else { CP_WAIT1(); }
        __syncwarp();
        const uint32_t bufB = warpB + (uint32_t)(ck & 1) * B_BUFW;
        const uint32_t aCk = aBase + (uint32_t)(ck * 16 * A_KSTR);

        uint32_t af[2][2][4];
        #pragma unroll
        for (int mt = 0; mt < 2; mt++) {
            ldsm4t(af[mt][0], aCk + mt * 32);          // hi plane
            ldsm4t(af[mt][1], aCk + mt * 32 + 64);     // lo plane
        }
        uint32_t b01[2][4], b2[2][2];
        #pragma unroll
        for (int hl = 0; hl < 2; hl++) {
            ldsm4(b01[hl], bufB + b4off + hl * 32);
            ldsm2(b2[hl],  bufB + b2off + hl * 32);
        }
        #pragma unroll
        for (int mt = 0; mt < 2; mt++) {
            #pragma unroll
            for (int j = 0; j < 3; j++) {
                const uint32_t* bh = (j < 2) ? &b01[0][j * 2] : b2[0];
                const uint32_t* bl = (j < 2) ? &b01[1][j * 2] : b2[1];
                mma16816(acc[mt][j], af[mt][0], bh);   // hi*hi
                mma16816(acc[mt][j], af[mt][1], bh);   // lo*hi
                mma16816(acc[mt][j], af[mt][0], bl);   // hi*lo
            }
        }
        if (ck < NCHUNK - 2) CP_CHUNK(ck + 2, ck & 1);
    }
    __syncthreads();   // all warps done with B region before res staging

    // --- stage accumulators to smem res[n][m], stride 33 floats ---
    float* res = (float*)(sm + OFF_B);
    {
        const int g = lane >> 2, tig = lane & 3;
        #pragma unroll
        for (int mt = 0; mt < 2; mt++) {
            #pragma unroll
            for (int j = 0; j < 3; j++) {
                int nb = n0 + j * 8 + tig * 2;
                int mb = mt * 16 + g;
                res[nb * 33 + mb]           = acc[mt][j][0];
                res[(nb + 1) * 33 + mb]     = acc[mt][j][1];
                res[nb * 33 + mb + 8]       = acc[mt][j][2];
                res[(nb + 1) * 33 + mb + 8] = acc[mt][j][3];
            }
        }
    }
    __syncthreads();

    // --- epilogue: (pm + w0) / (1 + |qa| + |qb|) ---
    for (int i = tid; i < Oo * TP; i += NTH) {
        int c = i >> 5, p = i & 31;
        float pm = res[c * 33 + p] + __ldg(w0v + c);
        float den = 1.0f + fabsf(res[(64 + c) * 33 + p])
                         + fabsf(res[(128 + c) * 33 + p]);
        out[(((size_t)b * Oo + c) * Hh + h) * Ww + w0i + p] = pm / den;
    }
    #undef CP_CHUNK
    #undef WIN_LOAD2
}

// ---------------------------------------------------------------------------
extern "C" void kernel_launch(void* const* d_in, const int* in_sizes, int n_in,
                              void* d_out, int out_size) {
    (void)in_sizes; (void)n_in; (void)out_size;
    const float* x     = (const float*)d_in[0];
    const float* off_w = (const float*)d_in[1];
    const float* off_b = (const float*)d_in[2];
    const float* w_m   = (const float*)d_in[3];
    const float* w_n   = (const float*)d_in[4];
    const float* w0    = (const float*)d_in[5];
    float* out = (float*)d_out;

    prep_kernel<<<(NOC * KTOT + 255) / 256, 256>>>(w_m, w_n);

    cudaFuncSetAttribute(pala_mma_kernel,
                         cudaFuncAttributeMaxDynamicSharedMemorySize, SMEM_BYTES);
    dim3 grid(Ww / TP, Hh, Bb);
    pala_mma_kernel<<<grid, NTH, SMEM_BYTES>>>(x, off_w, off_b, w0, out);
}